// round 13
// baseline (speedup 1.0000x reference)
#include <cuda_runtime.h>
#include <cuda_bf16.h>
#include <cstdint>

typedef unsigned long long ull;

// ---- PTX helpers (portable sm_80+) ----
__device__ __forceinline__ uint32_t s2u(const void* p){
  uint32_t a; asm("{ .reg .u64 t; cvta.to.shared.u64 t, %1; cvt.u32.u64 %0, t; }"
                  : "=r"(a) : "l"(p));
  return a;
}
__device__ __forceinline__ void ldsm4(uint32_t* r, uint32_t a){
  asm volatile("ldmatrix.sync.aligned.m8n8.x4.shared.b16 {%0,%1,%2,%3}, [%4];"
               : "=r"(r[0]), "=r"(r[1]), "=r"(r[2]), "=r"(r[3]) : "r"(a));
}
__device__ __forceinline__ void ldsm4t(uint32_t* r, uint32_t a){
  asm volatile("ldmatrix.sync.aligned.m8n8.x4.trans.shared.b16 {%0,%1,%2,%3}, [%4];"
               : "=r"(r[0]), "=r"(r[1]), "=r"(r[2]), "=r"(r[3]) : "r"(a));
}
__device__ __forceinline__ void mma16816(float* d, const uint32_t* a, const uint32_t* b){
  asm volatile(
    "mma.sync.aligned.m16n8k16.row.col.f32.bf16.bf16.f32 "
    "{%0,%1,%2,%3}, {%4,%5,%6,%7}, {%8,%9}, {%0,%1,%2,%3};"
    : "+f"(d[0]), "+f"(d[1]), "+f"(d[2]), "+f"(d[3])
    : "r"(a[0]), "r"(a[1]), "r"(a[2]), "r"(a[3]), "r"(b[0]), "r"(b[1]));
}
__device__ __forceinline__ void cpasync16(uint32_t dst, const void* src){
  asm volatile("cp.async.cg.shared.global [%0], [%1], 16;" :: "r"(dst), "l"(src) : "memory");
}
__device__ __forceinline__ float ex2f(float x){
  float y; asm("ex2.approx.ftz.f32 %0, %1;" : "=f"(y) : "f"(x)); return y;
}
template<int N> __device__ __forceinline__ void cpwait(){
  asm volatile("cp.async.wait_group %0;" :: "n"(N) : "memory");
}
#define CP_COMMIT() asm volatile("cp.async.commit_group;" ::: "memory")
#define CP_WAIT1()  asm volatile("cp.async.wait_group 1;" ::: "memory")
#define CP_WAIT0()  asm volatile("cp.async.wait_group 0;" ::: "memory")

#define SWZ(o)   ((o) ^ (((o) >> 3) & 0x70))   // SW128 (128B rows)
#define SWZ64(o) ((o) ^ (((o) >> 3) & 0x30))   // SW64  (64B rows)
#define C8L2E 11.541560327111707f   // 8 * log2(e)

// ======================= scratch (device globals) =======================
#define MR 8192
#define DD 1024
__device__ __nv_bfloat16 g_xlh[MR*DD], g_xll[MR*DD];
__device__ __nv_bfloat16 g_qkvh[MR*3*DD], g_qkvl[MR*3*DD];
__device__ __nv_bfloat16 g_oh[MR*DD], g_ol[MR*DD];
__device__ float g_x2[MR*DD];
__device__ __nv_bfloat16 g_hh[MR*4*DD], g_hl[MR*4*DD];
__device__ __nv_bfloat16 g_wqkvh[3*DD*DD], g_wqkvl[3*DD*DD];
__device__ __nv_bfloat16 g_wfh[DD*DD], g_wfl[DD*DD];
__device__ __nv_bfloat16 g_w1h[4*DD*DD], g_w1l[4*DD*DD];
__device__ __nv_bfloat16 g_w2h[4*DD*DD], g_w2l[4*DD*DD];

// ======================= LayerNorm -> bf16 hi/lo =======================
__global__ __launch_bounds__(256) void ln1024_split(
    const float* __restrict__ x, const float* __restrict__ g,
    const float* __restrict__ bt, __nv_bfloat16* __restrict__ yh,
    __nv_bfloat16* __restrict__ yl)
{
  int row = blockIdx.x;
  const float4* xr = (const float4*)(x + (size_t)row * 1024);
  float4 v = xr[threadIdx.x];
  float s = v.x + v.y + v.z + v.w;
  float q = v.x*v.x + v.y*v.y + v.z*v.z + v.w*v.w;
  #pragma unroll
  for (int off = 16; off; off >>= 1){
    s += __shfl_xor_sync(0xffffffffu, s, off);
    q += __shfl_xor_sync(0xffffffffu, q, off);
  }
  __shared__ float ss[8], qs[8];
  int w = threadIdx.x >> 5;
  if ((threadIdx.x & 31) == 0){ ss[w] = s; qs[w] = q; }
  __syncthreads();
  s = ss[0]+ss[1]+ss[2]+ss[3]+ss[4]+ss[5]+ss[6]+ss[7];
  q = qs[0]+qs[1]+qs[2]+qs[3]+qs[4]+qs[5]+qs[6]+qs[7];
  float mu   = s * (1.0f/1024.0f);
  float var  = q * (1.0f/1024.0f) - mu*mu;
  float rstd = rsqrtf(var + 1e-5f);
  int c = threadIdx.x * 4;
  float4 gg = *(const float4*)(g  + c);
  float4 bb = *(const float4*)(bt + c);
  float o0 = (v.x-mu)*rstd*gg.x + bb.x;
  float o1 = (v.y-mu)*rstd*gg.y + bb.y;
  float o2 = (v.z-mu)*rstd*gg.z + bb.z;
  float o3 = (v.w-mu)*rstd*gg.w + bb.w;
  __nv_bfloat16 h0=__float2bfloat16(o0), h1=__float2bfloat16(o1);
  __nv_bfloat16 h2=__float2bfloat16(o2), h3=__float2bfloat16(o3);
  __nv_bfloat162 ph0; ph0.x=h0; ph0.y=h1;
  __nv_bfloat162 ph1; ph1.x=h2; ph1.y=h3;
  __nv_bfloat162 pl0; pl0.x=__float2bfloat16(o0-__bfloat162float(h0));
                      pl0.y=__float2bfloat16(o1-__bfloat162float(h1));
  __nv_bfloat162 pl1; pl1.x=__float2bfloat16(o2-__bfloat162float(h2));
                      pl1.y=__float2bfloat16(o3-__bfloat162float(h3));
  size_t idx = (size_t)row*1024 + c;
  *(__nv_bfloat162*)(yh+idx)   = ph0; *(__nv_bfloat162*)(yh+idx+2) = ph1;
  *(__nv_bfloat162*)(yl+idx)   = pl0; *(__nv_bfloat162*)(yl+idx+2) = pl1;
}

// ======================= all weight transposes in ONE kernel =======================
__global__ void transp_split_all(
    const float* __restrict__ Wq, const float* __restrict__ Wk,
    const float* __restrict__ Wv, const float* __restrict__ Wfc,
    const float* __restrict__ W1, const float* __restrict__ W2,
    __nv_bfloat16* __restrict__ qkvh, __nv_bfloat16* __restrict__ qkvl,
    __nv_bfloat16* __restrict__ wfh,  __nv_bfloat16* __restrict__ wfl,
    __nv_bfloat16* __restrict__ w1h,  __nv_bfloat16* __restrict__ w1l,
    __nv_bfloat16* __restrict__ w2h,  __nv_bfloat16* __restrict__ w2l)
{
  int i = blockIdx.x;
  const float* W; __nv_bfloat16 *Th, *Tl; int K, N;
  if (i < 4096){
    K = 1024; N = 1024;
    int seg = i >> 10; i &= 1023;
    if      (seg == 0){ W = Wq;  Th = qkvh;              Tl = qkvl; }
    else if (seg == 1){ W = Wk;  Th = qkvh + 1048576;    Tl = qkvl + 1048576; }
    else if (seg == 2){ W = Wv;  Th = qkvh + 2097152;    Tl = qkvl + 2097152; }
    else              { W = Wfc; Th = wfh;               Tl = wfl; }
  } else if (i < 8192){ W = W1; Th = w1h; Tl = w1l; K = 1024; N = 4096; i -= 4096; }
  else                { W = W2; Th = w2h; Tl = w2l; K = 4096; N = 1024; i -= 8192; }
  int ntx = N >> 5;
  int n0 = (i % ntx) * 32, k0 = (i / ntx) * 32;

  __shared__ float t[32][33];
  int tx = threadIdx.x, ty = threadIdx.y; // 32 x 8
  #pragma unroll
  for (int j = 0; j < 4; j++)
    t[ty+8*j][tx] = W[(size_t)(k0+ty+8*j)*N + n0+tx];
  __syncthreads();
  #pragma unroll
  for (int j = 0; j < 4; j++){
    float v = t[tx][ty+8*j];
    __nv_bfloat16 h = __float2bfloat16(v);
    size_t idx = (size_t)(n0+ty+8*j)*K + k0+tx;
    Th[idx] = h;
    Tl[idx] = __float2bfloat16(v - __bfloat162float(h));
  }
}

// ======================= split-bf16 GEMM: K32 chunks, SW64, 4-stage ring ======
// CTA 128x256, 8 warps x 64x64. Stage (48KB): Ah 8K|Al 8K|Bh 16K|Bl 16K; 4 stages.
// Loads issued 3 chunks ahead; ONE __syncthreads per chunk (same sync count as
// the K64 2-stage scheme, but deeper DMA cover). Per-k16 MMA order unchanged.
__global__ __launch_bounds__(256, 1) void gemm_mma(
    const __nv_bfloat16* __restrict__ Ahi, const __nv_bfloat16* __restrict__ Alo,
    const __nv_bfloat16* __restrict__ Bhi, const __nv_bfloat16* __restrict__ Blo,
    const float* __restrict__ bias, const float* __restrict__ res,
    float* __restrict__ C, __nv_bfloat16* __restrict__ Chi,
    __nv_bfloat16* __restrict__ Clo,
    int M, int N, int K, int relu, int split)
{
  extern __shared__ __align__(1024) char smem[];
  const int tid = threadIdx.x, lane = tid & 31, wid = tid >> 5;
  const int m0 = blockIdx.y * 128, n0 = blockIdx.x * 256;
  const int wm = (wid >> 2) * 64, wn = (wid & 3) * 64;
  const uint32_t aS0 = s2u(smem);

  const int nc = K >> 5;   // K32 chunks

  float acc[4][8][4];
  #pragma unroll
  for (int i = 0; i < 4; i++)
    #pragma unroll
    for (int j = 0; j < 8; j++)
      #pragma unroll
      for (int r = 0; r < 4; r++) acc[i][j][r] = 0.f;

  const int rowA = lane & 15;
  const int kbA  = (lane & 16) ? 16 : 0;
  const int rowB = (lane & 7) + ((lane & 16) ? 8 : 0);
  const int kbB  = (lane & 8) ? 16 : 0;

  #define ISSUE(c) do { \
    int _k0 = (c) << 5; \
    uint32_t _st = aS0 + ((c) & 3) * 49152; \
    _Pragma("unroll") \
    for (int _i = 0; _i < 2; _i++){ \
      int _u = tid + 256*_i; int _r = _u >> 2, _cc = _u & 3; \
      uint32_t _d = SWZ64((uint32_t)(_r*64 + _cc*16)); \
      const size_t _src = (size_t)(m0 + _r) * K + _k0 + _cc*8; \
      cpasync16(_st + _d,        Ahi + _src); \
      cpasync16(_st + 8192 + _d, Alo + _src); \
    } \
    _Pragma("unroll") \
    for (int _i = 0; _i < 4; _i++){ \
      int _u = tid + 256*_i; int _r = _u >> 2, _cc = _u & 3; \
      uint32_t _d = SWZ64((uint32_t)(_r*64 + _cc*16)); \
      const size_t _src = (size_t)(n0 + _r) * K + _k0 + _cc*8; \
      cpasync16(_st + 16384 + _d, Bhi + _src); \
      cpasync16(_st + 32768 + _d, Blo + _src); \
    } \
    CP_COMMIT(); \
  } while(0)

  // prologue: 3 chunks in flight
  ISSUE(0);
  if (nc > 1) ISSUE(1);
  if (nc > 2) ISSUE(2);

  for (int c = 0; c < nc; c++){
    if (c == nc - 1)      cpwait<0>();
    else if (c == nc - 2) cpwait<1>();
    else                  cpwait<2>();
    __syncthreads();                 // chunk c visible; all readers of stage (c+3)&3 done
    if (c + 3 < nc) ISSUE(c + 3);
    const uint32_t st = aS0 + (c & 3) * 49152;
    #pragma unroll
    for (int s = 0; s < 2; s++){
      uint32_t ah[4][4], al[4][4], bh[4][4], bl[4][4];
      #pragma unroll
      for (int mi = 0; mi < 4; mi++){
        uint32_t off = SWZ64((uint32_t)((wm + mi*16 + rowA)*64 + s*32 + kbA));
        ldsm4(ah[mi], st + off);
        ldsm4(al[mi], st + 8192 + off);
      }
      #pragma unroll
      for (int njp = 0; njp < 4; njp++){
        uint32_t off = SWZ64((uint32_t)((wn + njp*16 + rowB)*64 + s*32 + kbB));
        ldsm4(bh[njp], st + 16384 + off);
        ldsm4(bl[njp], st + 32768 + off);
      }
      #pragma unroll
      for (int mi = 0; mi < 4; mi++)
        #pragma unroll
        for (int nj = 0; nj < 8; nj++)
          mma16816(acc[mi][nj], ah[mi], &bh[nj >> 1][(nj & 1) * 2]);
      #pragma unroll
      for (int mi = 0; mi < 4; mi++)
        #pragma unroll
        for (int nj = 0; nj < 8; nj++)
          mma16816(acc[mi][nj], ah[mi], &bl[nj >> 1][(nj & 1) * 2]);
      #pragma unroll
      for (int mi = 0; mi < 4; mi++)
        #pragma unroll
        for (int nj = 0; nj < 8; nj++)
          mma16816(acc[mi][nj], al[mi], &bh[nj >> 1][(nj & 1) * 2]);
    }
  }
  #undef ISSUE

  const int er = lane >> 2, ec = (lane & 3) * 2;
  #pragma unroll
  for (int mi = 0; mi < 4; mi++){
    #pragma unroll
    for (int half = 0; half < 2; half++){
      int row = m0 + wm + mi*16 + er + half*8;
      #pragma unroll
      for (int nj = 0; nj < 8; nj++){
        int col = n0 + wn + nj*8 + ec;
        float v0 = acc[mi][nj][half*2 + 0];
        float v1 = acc[mi][nj][half*2 + 1];
        if (bias){
          float2 bv = *(const float2*)(bias + col);
          v0 += bv.x; v1 += bv.y;
        }
        if (relu){ v0 = fmaxf(v0, 0.f); v1 = fmaxf(v1, 0.f); }
        if (res){
          float2 rv = *(const float2*)(res + (size_t)row*N + col);
          v0 += rv.x; v1 += rv.y;
        }
        size_t idx = (size_t)row*N + col;
        if (split){
          __nv_bfloat16 h0 = __float2bfloat16(v0), h1 = __float2bfloat16(v1);
          __nv_bfloat162 ph; ph.x = h0; ph.y = h1;
          __nv_bfloat162 pl;
          pl.x = __float2bfloat16(v0 - __bfloat162float(h0));
          pl.y = __float2bfloat16(v1 - __bfloat162float(h1));
          *(__nv_bfloat162*)(Chi + idx) = ph;
          *(__nv_bfloat162*)(Clo + idx) = pl;
        } else {
          float2 o; o.x = v0; o.y = v1;
          *(float2*)(C + idx) = o;
        }
      }
    }
  }
}

// ======================= flash attention: pipelined scores (round-11) =======================
__global__ __launch_bounds__(256, 1) void attn_mma(
    const __nv_bfloat16* __restrict__ QKVh, const __nv_bfloat16* __restrict__ QKVl,
    __nv_bfloat16* __restrict__ Oh, __nv_bfloat16* __restrict__ Ol)
{
  extern __shared__ __align__(1024) char smem[];
  const int tid = threadIdx.x, lane = tid & 31, warp = tid >> 5;
  const int b = blockIdx.z, h = blockIdx.y, q0 = blockIdx.x * 128;
  const size_t baseq = ((size_t)b * 2048) * 3072 + h * 64;
  const size_t baseo = ((size_t)b * 2048) * 1024 + h * 64;
  const uint32_t aQ = s2u(smem);
  const uint32_t aKV = aQ + 32768;       // 4 stages x 32KB
  const int wm = warp * 16;

  const int rowA = lane & 15;
  const int kbA  = (lane & 16) ? 16 : 0;
  const int rowB = (lane & 7) + ((lane & 16) ? 8 : 0);
  const int kbB  = (lane & 8) ? 16 : 0;
  const int kvr  = lane & 15;
  const int ncb  = (lane & 16) ? 8 : 0;

  #pragma unroll
  for (int i = 0; i < 4; i++){
    int gg = tid + 256*i;
    int r = gg >> 3, c = gg & 7;
    uint32_t d = SWZ((uint32_t)(r*128 + c*16));
    const size_t src = baseq + (size_t)(q0 + r) * 3072 + c*8;
    cpasync16(aQ + d, QKVh + src);
    cpasync16(aQ + 16384 + d, QKVl + src);
  }
  CP_COMMIT();

  #define ISSUEKV(j) do { \
    uint32_t _st = aKV + ((j) & 3) * 32768; \
    int _j0 = (j) * 64; \
    _Pragma("unroll") \
    for (int _i = 0; _i < 2; _i++){ \
      int _gg = tid + 256*_i; \
      int _r = _gg >> 3, _c = _gg & 7; \
      uint32_t _d = SWZ((uint32_t)(_r*128 + _c*16)); \
      const size_t _srcK = baseq + 1024 + (size_t)(_j0 + _r) * 3072 + _c*8; \
      const size_t _srcV = baseq + 2048 + (size_t)(_j0 + _r) * 3072 + _c*8; \
      cpasync16(_st + _d,         QKVh + _srcK); \
      cpasync16(_st + 8192 + _d,  QKVl + _srcK); \
      cpasync16(_st + 16384 + _d, QKVh + _srcV); \
      cpasync16(_st + 24576 + _d, QKVl + _srcV); \
    } \
    CP_COMMIT(); \
  } while(0)

  uint32_t qfh[4][4], qfl[4][4];
  float m0 = -1e30f, m1 = -1e30f, l0 = 0.f, l1 = 0.f;
  float oa[8][4];
  #pragma unroll
  for (int nb = 0; nb < 8; nb++)
    #pragma unroll
    for (int r = 0; r < 4; r++) oa[nb][r] = 0.f;

  float scA[8][4], scB[8][4];

  #define SCORE(t, SC) do { \
    const uint32_t _st = aKV + ((t) & 3) * 32768; \
    _Pragma("unroll") \
    for (int _nb = 0; _nb < 8; _nb++) \
      _Pragma("unroll") \
      for (int _r = 0; _r < 4; _r++) SC[_nb][_r] = 0.f; \
    _Pragma("unroll") \
    for (int _s = 0; _s < 4; _s++){ \
      uint32_t _kh[4][4], _kl[4][4]; \
      _Pragma("unroll") \
      for (int _g = 0; _g < 4; _g++){ \
        uint32_t _off = SWZ((uint32_t)((_g*16 + rowB)*128 + _s*32 + kbB)); \
        ldsm4(_kh[_g], _st + _off); \
        ldsm4(_kl[_g], _st + 8192 + _off); \
      } \
      _Pragma("unroll") \
      for (int _g = 0; _g < 4; _g++){ \
        mma16816(SC[2*_g],   qfh[_s], _kh[_g]); \
        mma16816(SC[2*_g+1], qfh[_s], _kh[_g] + 2); \
        mma16816(SC[2*_g],   qfl[_s], _kh[_g]); \
        mma16816(SC[2*_g+1], qfl[_s], _kh[_g] + 2); \
        mma16816(SC[2*_g],   qfh[_s], _kl[_g]); \
        mma16816(SC[2*_g+1], qfh[_s], _kl[_g] + 2); \
      } \
    } \
  } while(0)

  #define STEP(t, CUR, NXT) do { \
    if ((t) + 2 < 32){ ISSUEKV((t) + 2); CP_WAIT1(); } \
    else if ((t) + 1 < 32){ CP_WAIT0(); } \
    __syncthreads(); \
    if ((t) + 1 < 32) SCORE((t) + 1, NXT); \
    float mx0 = -1e30f, mx1 = -1e30f; \
    _Pragma("unroll") \
    for (int nb = 0; nb < 8; nb++){ \
      mx0 = fmaxf(mx0, fmaxf(CUR[nb][0], CUR[nb][1])); \
      mx1 = fmaxf(mx1, fmaxf(CUR[nb][2], CUR[nb][3])); \
    } \
    mx0 = fmaxf(mx0, __shfl_xor_sync(0xffffffffu, mx0, 1)); \
    mx0 = fmaxf(mx0, __shfl_xor_sync(0xffffffffu, mx0, 2)); \
    mx1 = fmaxf(mx1, __shfl_xor_sync(0xffffffffu, mx1, 1)); \
    mx1 = fmaxf(mx1, __shfl_xor_sync(0xffffffffu, mx1, 2)); \
    float nm0 = fmaxf(m0, mx0), nm1 = fmaxf(m1, mx1); \
    float a0 = ex2f((m0 - nm0) * C8L2E), a1 = ex2f((m1 - nm1) * C8L2E); \
    m0 = nm0; m1 = nm1; \
    float c0 = nm0 * C8L2E, c1 = nm1 * C8L2E; \
    float rs0 = 0.f, rs1 = 0.f; \
    uint32_t pfh[4][4], pfl[4][4]; \
    _Pragma("unroll") \
    for (int nb = 0; nb < 8; nb++){ \
      float p00 = ex2f(fmaf(CUR[nb][0], C8L2E, -c0)); \
      float p01 = ex2f(fmaf(CUR[nb][1], C8L2E, -c0)); \
      float p10 = ex2f(fmaf(CUR[nb][2], C8L2E, -c1)); \
      float p11 = ex2f(fmaf(CUR[nb][3], C8L2E, -c1)); \
      rs0 += p00 + p01; rs1 += p10 + p11; \
      __nv_bfloat162 h0 = __floats2bfloat162_rn(p00, p01); \
      __nv_bfloat162 h1 = __floats2bfloat162_rn(p10, p11); \
      __nv_bfloat162 lo0 = __floats2bfloat162_rn(p00 - __bfloat162float(h0.x), \
                                                 p01 - __bfloat162float(h0.y)); \
      __nv_bfloat162 lo1 = __floats2bfloat162_rn(p10 - __bfloat162float(h1.x), \
                                                 p11 - __bfloat162float(h1.y)); \
      int j = nb >> 1, rq = (nb & 1) * 2; \
      pfh[j][rq]   = *(uint32_t*)&h0;  pfh[j][rq+1] = *(uint32_t*)&h1; \
      pfl[j][rq]   = *(uint32_t*)&lo0; pfl[j][rq+1] = *(uint32_t*)&lo1; \
    } \
    rs0 += __shfl_xor_sync(0xffffffffu, rs0, 1); \
    rs0 += __shfl_xor_sync(0xffffffffu, rs0, 2); \
    rs1 += __shfl_xor_sync(0xffffffffu, rs1, 1); \
    rs1 += __shfl_xor_sync(0xffffffffu, rs1, 2); \
    l0 = l0 * a0 + rs0; l1 = l1 * a1 + rs1; \
    _Pragma("unroll") \
    for (int nb = 0; nb < 8; nb++){ \
      oa[nb][0] *= a0; oa[nb][1] *= a0; oa[nb][2] *= a1; oa[nb][3] *= a1; \
    } \
    const uint32_t _pst = aKV + ((t) & 3) * 32768; \
    _Pragma("unroll") \
    for (int _s = 0; _s < 4; _s++){ \
      uint32_t _vh[4][4], _vl[4][4]; \
      _Pragma("unroll") \
      for (int _g = 0; _g < 4; _g++){ \
        uint32_t _off = SWZ((uint32_t)((_s*16 + kvr)*128 + (_g*16 + ncb)*2)); \
        ldsm4t(_vh[_g], _pst + 16384 + _off); \
        ldsm4t(_vl[_g], _pst + 24576 + _off); \
      } \
      _Pragma("unroll") \
      for (int _g = 0; _g < 4; _g++){ \
        mma16816(oa[2*_g],   pfh[_s], _vh[_g]); \
        mma16816(oa[2*_g+1], pfh[_s], _vh[_g] + 2); \
        mma16816(oa[2*_g],   pfl[_s], _vh[_g]); \
        mma16816(oa[2*_g+1], pfl[_s], _vh[_g] + 2); \
        mma16816(oa[2*_g],   pfh[_s], _vl[_g]); \
        mma16816(oa[2*_g+1], pfh[_s], _vl[_g] + 2); \
      } \
    } \
  } while(0)

  ISSUEKV(0); ISSUEKV(1);
  CP_WAIT1();
  __syncthreads();
  #pragma unroll
  for (int s = 0; s < 4; s++){
    uint32_t off = SWZ((uint32_t)((wm + rowA)*128 + s*32 + kbA));
    ldsm4(qfh[s], aQ + off);
    ldsm4(qfl[s], aQ + 16384 + off);
  }
  SCORE(0, scA);

  #pragma unroll 1
  for (int jt = 0; jt < 32; jt += 2){
    STEP(jt,     scA, scB);
    STEP(jt + 1, scB, scA);
  }
  #undef STEP
  #undef SCORE
  #undef ISSUEKV

  const int er = lane >> 2, ec = (lane & 3) * 2;
  float i0 = 1.0f / l0, i1 = 1.0f / l1;
  const int r0 = q0 + wm + er;
  #pragma unroll
  for (int nb = 0; nb < 8; nb++){
    int col = nb*8 + ec;
    float v0 = oa[nb][0]*i0, v1 = oa[nb][1]*i0;
    float v2 = oa[nb][2]*i1, v3 = oa[nb][3]*i1;
    __nv_bfloat162 h0 = __floats2bfloat162_rn(v0, v1);
    __nv_bfloat162 h1 = __floats2bfloat162_rn(v2, v3);
    __nv_bfloat162 lo0 = __floats2bfloat162_rn(v0 - __bfloat162float(h0.x),
                                               v1 - __bfloat162float(h0.y));
    __nv_bfloat162 lo1 = __floats2bfloat162_rn(v2 - __bfloat162float(h1.x),
                                               v3 - __bfloat162float(h1.y));
    size_t i0x = baseo + (size_t)r0 * 1024 + col;
    size_t i1x = baseo + (size_t)(r0 + 8) * 1024 + col;
    *(__nv_bfloat162*)(Oh + i0x) = h0;
    *(__nv_bfloat162*)(Ol + i0x) = lo0;
    *(__nv_bfloat162*)(Oh + i1x) = h1;
    *(__nv_bfloat162*)(Ol + i1x) = lo1;
  }
}

// ======================= launch =======================
extern "C" void kernel_launch(void* const* d_in, const int* in_sizes, int n_in,
                              void* d_out, int out_size)
{
  (void)in_sizes; (void)n_in; (void)out_size;
  const float* x   = (const float*)d_in[0];
  const float* Wk  = (const float*)d_in[2];
  const float* Wq  = (const float*)d_in[3];
  const float* Wv  = (const float*)d_in[4];
  const float* Wfc = (const float*)d_in[5];
  const float* bfc = (const float*)d_in[6];
  const float* g1  = (const float*)d_in[7];
  const float* b1  = (const float*)d_in[8];
  const float* g2  = (const float*)d_in[9];
  const float* b2  = (const float*)d_in[10];
  const float* W1  = (const float*)d_in[11];
  const float* bf1 = (const float*)d_in[12];
  const float* W2  = (const float*)d_in[13];
  const float* bf2 = (const float*)d_in[14];
  float* out = (float*)d_out;

  __nv_bfloat16 *xlh,*xll,*qkvh,*qkvl,*oh,*ol,*hh,*hl;
  __nv_bfloat16 *wqkvh,*wqkvl,*wfh,*wfl,*w1h,*w1l,*w2h,*w2l;
  float *x2;
  cudaGetSymbolAddress((void**)&xlh, g_xlh); cudaGetSymbolAddress((void**)&xll, g_xll);
  cudaGetSymbolAddress((void**)&qkvh, g_qkvh); cudaGetSymbolAddress((void**)&qkvl, g_qkvl);
  cudaGetSymbolAddress((void**)&oh, g_oh); cudaGetSymbolAddress((void**)&ol, g_ol);
  cudaGetSymbolAddress((void**)&x2, g_x2);
  cudaGetSymbolAddress((void**)&hh, g_hh); cudaGetSymbolAddress((void**)&hl, g_hl);
  cudaGetSymbolAddress((void**)&wqkvh, g_wqkvh); cudaGetSymbolAddress((void**)&wqkvl, g_wqkvl);
  cudaGetSymbolAddress((void**)&wfh, g_wfh); cudaGetSymbolAddress((void**)&wfl, g_wfl);
  cudaGetSymbolAddress((void**)&w1h, g_w1h); cudaGetSymbolAddress((void**)&w1l, g_w1l);
  cudaGetSymbolAddress((void**)&w2h, g_w2h); cudaGetSymbolAddress((void**)&w2l, g_w2l);

  static int smem_set = 0;
  if (!smem_set){
    cudaFuncSetAttribute(gemm_mma, cudaFuncAttributeMaxDynamicSharedMemorySize, 196608);
    cudaFuncSetAttribute(attn_mma, cudaFuncAttributeMaxDynamicSharedMemorySize, 163840);
    smem_set = 1;
  }

  const int M = 8192, D = 1024;
  const int GSM = 196608;   // 4 stages x 48KB
  const int ASM = 163840;   // Q 32KB + 4x32KB KV ring
  dim3 tb(32, 8);

  transp_split_all<<<12288, tb>>>(Wq, Wk, Wv, Wfc, W1, W2,
                                  wqkvh, wqkvl, wfh, wfl, w1h, w1l, w2h, w2l);

  dim3 gQKV(3*D/256, M/128);   // (12, 64)
  dim3 gD(D/256, M/128);       // (4, 64)
  dim3 gF(4*D/256, M/128);     // (16, 64)

  ln1024_split<<<M, 256>>>(x, g1, b1, xlh, xll);
  gemm_mma<<<gQKV, 256, GSM>>>(xlh, xll, wqkvh, wqkvl, nullptr, nullptr, nullptr,
                               qkvh, qkvl, M, 3*D, D, 0, 1);
  attn_mma<<<dim3(16, 16, 4), 256, ASM>>>(qkvh, qkvl, oh, ol);
  gemm_mma<<<gD, 256, GSM>>>(oh, ol, wfh, wfl, bfc, x, x2, nullptr, nullptr,
                             M, D, D, 0, 0);
  ln1024_split<<<M, 256>>>(x2, g2, b2, xlh, xll);
  gemm_mma<<<gF, 256, GSM>>>(xlh, xll, w1h, w1l, bf1, nullptr, nullptr, hh, hl,
                             M, 4*D, D, 1, 1);
  gemm_mma<<<gD, 256, GSM>>>(hh, hl, w2h, w2l, bf2, x2, out, nullptr, nullptr,
                             M, D, 4*D, 0, 0);
}

// round 14
// speedup vs baseline: 1.6710x; 1.6710x over previous
#include <cuda_runtime.h>
#include <cuda_bf16.h>
#include <cstdint>

typedef unsigned long long ull;

// ---- PTX helpers (portable sm_80+) ----
__device__ __forceinline__ uint32_t s2u(const void* p){
  uint32_t a; asm("{ .reg .u64 t; cvta.to.shared.u64 t, %1; cvt.u32.u64 %0, t; }"
                  : "=r"(a) : "l"(p));
  return a;
}
__device__ __forceinline__ void ldsm4(uint32_t* r, uint32_t a){
  asm volatile("ldmatrix.sync.aligned.m8n8.x4.shared.b16 {%0,%1,%2,%3}, [%4];"
               : "=r"(r[0]), "=r"(r[1]), "=r"(r[2]), "=r"(r[3]) : "r"(a));
}
__device__ __forceinline__ void ldsm4t(uint32_t* r, uint32_t a){
  asm volatile("ldmatrix.sync.aligned.m8n8.x4.trans.shared.b16 {%0,%1,%2,%3}, [%4];"
               : "=r"(r[0]), "=r"(r[1]), "=r"(r[2]), "=r"(r[3]) : "r"(a));
}
__device__ __forceinline__ void mma16816(float* d, const uint32_t* a, const uint32_t* b){
  asm volatile(
    "mma.sync.aligned.m16n8k16.row.col.f32.bf16.bf16.f32 "
    "{%0,%1,%2,%3}, {%4,%5,%6,%7}, {%8,%9}, {%0,%1,%2,%3};"
    : "+f"(d[0]), "+f"(d[1]), "+f"(d[2]), "+f"(d[3])
    : "r"(a[0]), "r"(a[1]), "r"(a[2]), "r"(a[3]), "r"(b[0]), "r"(b[1]));
}
__device__ __forceinline__ void cpasync16(uint32_t dst, const void* src){
  asm volatile("cp.async.cg.shared.global [%0], [%1], 16;" :: "r"(dst), "l"(src) : "memory");
}
__device__ __forceinline__ float ex2f(float x){
  float y; asm("ex2.approx.ftz.f32 %0, %1;" : "=f"(y) : "f"(x)); return y;
}
#define CP_COMMIT() asm volatile("cp.async.commit_group;" ::: "memory")
#define CP_WAIT1()  asm volatile("cp.async.wait_group 1;" ::: "memory")
#define CP_WAIT0()  asm volatile("cp.async.wait_group 0;" ::: "memory")

#define SWZ(o) ((o) ^ (((o) >> 3) & 0x70))
#define C8L2E 11.541560327111707f   // 8 * log2(e)

// ======================= scratch (device globals) =======================
#define MR 8192
#define DD 1024
__device__ __nv_bfloat16 g_xlh[MR*DD], g_xll[MR*DD];
__device__ __nv_bfloat16 g_qkvh[MR*3*DD], g_qkvl[MR*3*DD];
__device__ __nv_bfloat16 g_oh[MR*DD], g_ol[MR*DD];
__device__ float g_x2[MR*DD];
__device__ __nv_bfloat16 g_hh[MR*4*DD], g_hl[MR*4*DD];
__device__ __nv_bfloat16 g_wqkvh[3*DD*DD], g_wqkvl[3*DD*DD];
__device__ __nv_bfloat16 g_wfh[DD*DD], g_wfl[DD*DD];
__device__ __nv_bfloat16 g_w1h[4*DD*DD], g_w1l[4*DD*DD];
__device__ __nv_bfloat16 g_w2h[4*DD*DD], g_w2l[4*DD*DD];

// ======================= LN row helper =======================
__device__ __forceinline__ void ln_row(
    int row, int tid, const float* __restrict__ x, const float* __restrict__ g,
    const float* __restrict__ bt, __nv_bfloat16* __restrict__ yh,
    __nv_bfloat16* __restrict__ yl, float* ss, float* qs)
{
  const float4* xr = (const float4*)(x + (size_t)row * 1024);
  float4 v = xr[tid];
  float s = v.x + v.y + v.z + v.w;
  float q = v.x*v.x + v.y*v.y + v.z*v.z + v.w*v.w;
  #pragma unroll
  for (int off = 16; off; off >>= 1){
    s += __shfl_xor_sync(0xffffffffu, s, off);
    q += __shfl_xor_sync(0xffffffffu, q, off);
  }
  int w = tid >> 5;
  if ((tid & 31) == 0){ ss[w] = s; qs[w] = q; }
  __syncthreads();
  s = ss[0]+ss[1]+ss[2]+ss[3]+ss[4]+ss[5]+ss[6]+ss[7];
  q = qs[0]+qs[1]+qs[2]+qs[3]+qs[4]+qs[5]+qs[6]+qs[7];
  float mu   = s * (1.0f/1024.0f);
  float var  = q * (1.0f/1024.0f) - mu*mu;
  float rstd = rsqrtf(var + 1e-5f);
  int c = tid * 4;
  float4 gg = *(const float4*)(g  + c);
  float4 bb = *(const float4*)(bt + c);
  float o0 = (v.x-mu)*rstd*gg.x + bb.x;
  float o1 = (v.y-mu)*rstd*gg.y + bb.y;
  float o2 = (v.z-mu)*rstd*gg.z + bb.z;
  float o3 = (v.w-mu)*rstd*gg.w + bb.w;
  __nv_bfloat16 h0=__float2bfloat16(o0), h1=__float2bfloat16(o1);
  __nv_bfloat16 h2=__float2bfloat16(o2), h3=__float2bfloat16(o3);
  __nv_bfloat162 ph0; ph0.x=h0; ph0.y=h1;
  __nv_bfloat162 ph1; ph1.x=h2; ph1.y=h3;
  __nv_bfloat162 pl0; pl0.x=__float2bfloat16(o0-__bfloat162float(h0));
                      pl0.y=__float2bfloat16(o1-__bfloat162float(h1));
  __nv_bfloat162 pl1; pl1.x=__float2bfloat16(o2-__bfloat162float(h2));
                      pl1.y=__float2bfloat16(o3-__bfloat162float(h3));
  size_t idx = (size_t)row*1024 + c;
  *(__nv_bfloat162*)(yh+idx)   = ph0; *(__nv_bfloat162*)(yh+idx+2) = ph1;
  *(__nv_bfloat162*)(yl+idx)   = pl0; *(__nv_bfloat162*)(yl+idx+2) = pl1;
}

__global__ __launch_bounds__(256) void ln1024_split(
    const float* __restrict__ x, const float* __restrict__ g,
    const float* __restrict__ bt, __nv_bfloat16* __restrict__ yh,
    __nv_bfloat16* __restrict__ yl)
{
  __shared__ float ss[8], qs[8];
  ln_row(blockIdx.x, threadIdx.x, x, g, bt, yh, yl, ss, qs);
}

// ======================= weight transposes + LN1 fused in ONE kernel ==============
// blocks [0, 12288): weight transpose+split; blocks [12288, 20480): LN1 rows.
__global__ __launch_bounds__(256) void prep_all(
    const float* __restrict__ Wq, const float* __restrict__ Wk,
    const float* __restrict__ Wv, const float* __restrict__ Wfc,
    const float* __restrict__ W1, const float* __restrict__ W2,
    __nv_bfloat16* __restrict__ qkvh, __nv_bfloat16* __restrict__ qkvl,
    __nv_bfloat16* __restrict__ wfh,  __nv_bfloat16* __restrict__ wfl,
    __nv_bfloat16* __restrict__ w1h,  __nv_bfloat16* __restrict__ w1l,
    __nv_bfloat16* __restrict__ w2h,  __nv_bfloat16* __restrict__ w2l,
    const float* __restrict__ x, const float* __restrict__ g1,
    const float* __restrict__ b1, __nv_bfloat16* __restrict__ xlh,
    __nv_bfloat16* __restrict__ xll)
{
  int tx = threadIdx.x & 31, ty = threadIdx.x >> 5;   // 32 x 8
  int i = blockIdx.x;

  if (i >= 12288){   // LN1 rows
    __shared__ float ss[8], qs[8];
    ln_row(i - 12288, threadIdx.x, x, g1, b1, xlh, xll, ss, qs);
    return;
  }

  const float* W; __nv_bfloat16 *Th, *Tl; int K, N;
  if (i < 4096){
    K = 1024; N = 1024;
    int seg = i >> 10; i &= 1023;
    if      (seg == 0){ W = Wq;  Th = qkvh;              Tl = qkvl; }
    else if (seg == 1){ W = Wk;  Th = qkvh + 1048576;    Tl = qkvl + 1048576; }
    else if (seg == 2){ W = Wv;  Th = qkvh + 2097152;    Tl = qkvl + 2097152; }
    else              { W = Wfc; Th = wfh;               Tl = wfl; }
  } else if (i < 8192){ W = W1; Th = w1h; Tl = w1l; K = 1024; N = 4096; i -= 4096; }
  else                { W = W2; Th = w2h; Tl = w2l; K = 4096; N = 1024; i -= 8192; }
  int ntx = N >> 5;
  int n0 = (i % ntx) * 32, k0 = (i / ntx) * 32;

  __shared__ float t[32][33];
  #pragma unroll
  for (int j = 0; j < 4; j++)
    t[ty+8*j][tx] = W[(size_t)(k0+ty+8*j)*N + n0+tx];
  __syncthreads();
  #pragma unroll
  for (int j = 0; j < 4; j++){
    float v = t[tx][ty+8*j];
    __nv_bfloat16 h = __float2bfloat16(v);
    size_t idx = (size_t)(n0+ty+8*j)*K + k0+tx;
    Th[idx] = h;
    Tl[idx] = __float2bfloat16(v - __bfloat162float(h));
  }
}

// ======================= split-bf16 GEMM (round-11 config: 128x256, 2x96KB) ======
__global__ __launch_bounds__(256, 1) void gemm_mma(
    const __nv_bfloat16* __restrict__ Ahi, const __nv_bfloat16* __restrict__ Alo,
    const __nv_bfloat16* __restrict__ Bhi, const __nv_bfloat16* __restrict__ Blo,
    const float* __restrict__ bias, const float* __restrict__ res,
    float* __restrict__ C, __nv_bfloat16* __restrict__ Chi,
    __nv_bfloat16* __restrict__ Clo,
    int M, int N, int K, int relu, int split)
{
  extern __shared__ __align__(1024) char smem[];
  const int tid = threadIdx.x, lane = tid & 31, wid = tid >> 5;
  const int m0 = blockIdx.y * 128, n0 = blockIdx.x * 256;
  const int wm = (wid >> 2) * 64, wn = (wid & 3) * 64;
  const uint32_t aS0 = s2u(smem);

  const int nc = K >> 6;

  float acc[4][8][4];
  #pragma unroll
  for (int i = 0; i < 4; i++)
    #pragma unroll
    for (int j = 0; j < 8; j++)
      #pragma unroll
      for (int r = 0; r < 4; r++) acc[i][j][r] = 0.f;

  const int rowA = lane & 15;
  const int kbA  = (lane & 16) ? 16 : 0;
  const int rowB = (lane & 7) + ((lane & 16) ? 8 : 0);
  const int kbB  = (lane & 8) ? 16 : 0;

  #define ISSUE(c) do { \
    int _k0 = (c) << 6; \
    uint32_t _st = aS0 + ((c) & 1) * 98304; \
    _Pragma("unroll") \
    for (int _i = 0; _i < 4; _i++){ \
      int _gg = tid + 256*_i; int _r = _gg >> 3, _c = _gg & 7; \
      uint32_t _d = SWZ((uint32_t)(_r*128 + _c*16)); \
      const size_t _src = (size_t)(m0 + _r) * K + _k0 + _c*8; \
      cpasync16(_st + _d,         Ahi + _src); \
      cpasync16(_st + 16384 + _d, Alo + _src); \
    } \
    _Pragma("unroll") \
    for (int _i = 0; _i < 8; _i++){ \
      int _gg = tid + 256*_i; int _r = _gg >> 3, _c = _gg & 7; \
      uint32_t _d = SWZ((uint32_t)(_r*128 + _c*16)); \
      const size_t _src = (size_t)(n0 + _r) * K + _k0 + _c*8; \
      cpasync16(_st + 32768 + _d, Bhi + _src); \
      cpasync16(_st + 65536 + _d, Blo + _src); \
    } \
    CP_COMMIT(); \
  } while(0)

  ISSUE(0);
  for (int c = 0; c < nc; c++){
    __syncthreads();
    if (c + 1 < nc){ ISSUE(c + 1); CP_WAIT1(); }
    else           { CP_WAIT0(); }
    __syncthreads();
    const uint32_t st = aS0 + (c & 1) * 98304;
    #pragma unroll
    for (int s = 0; s < 4; s++){
      uint32_t ah[4][4], al[4][4], bh[4][4], bl[4][4];
      #pragma unroll
      for (int mi = 0; mi < 4; mi++){
        uint32_t off = SWZ((uint32_t)((wm + mi*16 + rowA)*128 + s*32 + kbA));
        ldsm4(ah[mi], st + off);
        ldsm4(al[mi], st + 16384 + off);
      }
      #pragma unroll
      for (int njp = 0; njp < 4; njp++){
        uint32_t off = SWZ((uint32_t)((wn + njp*16 + rowB)*128 + s*32 + kbB));
        ldsm4(bh[njp], st + 32768 + off);
        ldsm4(bl[njp], st + 65536 + off);
      }
      #pragma unroll
      for (int mi = 0; mi < 4; mi++)
        #pragma unroll
        for (int nj = 0; nj < 8; nj++)
          mma16816(acc[mi][nj], ah[mi], &bh[nj >> 1][(nj & 1) * 2]);
      #pragma unroll
      for (int mi = 0; mi < 4; mi++)
        #pragma unroll
        for (int nj = 0; nj < 8; nj++)
          mma16816(acc[mi][nj], ah[mi], &bl[nj >> 1][(nj & 1) * 2]);
      #pragma unroll
      for (int mi = 0; mi < 4; mi++)
        #pragma unroll
        for (int nj = 0; nj < 8; nj++)
          mma16816(acc[mi][nj], al[mi], &bh[nj >> 1][(nj & 1) * 2]);
    }
  }
  #undef ISSUE

  const int er = lane >> 2, ec = (lane & 3) * 2;
  #pragma unroll
  for (int mi = 0; mi < 4; mi++){
    #pragma unroll
    for (int half = 0; half < 2; half++){
      int row = m0 + wm + mi*16 + er + half*8;
      #pragma unroll
      for (int nj = 0; nj < 8; nj++){
        int col = n0 + wn + nj*8 + ec;
        float v0 = acc[mi][nj][half*2 + 0];
        float v1 = acc[mi][nj][half*2 + 1];
        if (bias){
          float2 bv = *(const float2*)(bias + col);
          v0 += bv.x; v1 += bv.y;
        }
        if (relu){ v0 = fmaxf(v0, 0.f); v1 = fmaxf(v1, 0.f); }
        if (res){
          float2 rv = *(const float2*)(res + (size_t)row*N + col);
          v0 += rv.x; v1 += rv.y;
        }
        size_t idx = (size_t)row*N + col;
        if (split){
          __nv_bfloat16 h0 = __float2bfloat16(v0), h1 = __float2bfloat16(v1);
          __nv_bfloat162 ph; ph.x = h0; ph.y = h1;
          __nv_bfloat162 pl;
          pl.x = __float2bfloat16(v0 - __bfloat162float(h0));
          pl.y = __float2bfloat16(v1 - __bfloat162float(h1));
          *(__nv_bfloat162*)(Chi + idx) = ph;
          *(__nv_bfloat162*)(Clo + idx) = pl;
        } else {
          float2 o; o.x = v0; o.y = v1;
          *(float2*)(C + idx) = o;
        }
      }
    }
  }
}

// ======================= flash attention: pipelined scores (round-11) =======================
__global__ __launch_bounds__(256, 1) void attn_mma(
    const __nv_bfloat16* __restrict__ QKVh, const __nv_bfloat16* __restrict__ QKVl,
    __nv_bfloat16* __restrict__ Oh, __nv_bfloat16* __restrict__ Ol)
{
  extern __shared__ __align__(1024) char smem[];
  const int tid = threadIdx.x, lane = tid & 31, warp = tid >> 5;
  const int b = blockIdx.z, h = blockIdx.y, q0 = blockIdx.x * 128;
  const size_t baseq = ((size_t)b * 2048) * 3072 + h * 64;
  const size_t baseo = ((size_t)b * 2048) * 1024 + h * 64;
  const uint32_t aQ = s2u(smem);
  const uint32_t aKV = aQ + 32768;       // 4 stages x 32KB
  const int wm = warp * 16;

  const int rowA = lane & 15;
  const int kbA  = (lane & 16) ? 16 : 0;
  const int rowB = (lane & 7) + ((lane & 16) ? 8 : 0);
  const int kbB  = (lane & 8) ? 16 : 0;
  const int kvr  = lane & 15;
  const int ncb  = (lane & 16) ? 8 : 0;

  #pragma unroll
  for (int i = 0; i < 4; i++){
    int gg = tid + 256*i;
    int r = gg >> 3, c = gg & 7;
    uint32_t d = SWZ((uint32_t)(r*128 + c*16));
    const size_t src = baseq + (size_t)(q0 + r) * 3072 + c*8;
    cpasync16(aQ + d, QKVh + src);
    cpasync16(aQ + 16384 + d, QKVl + src);
  }
  CP_COMMIT();

  #define ISSUEKV(j) do { \
    uint32_t _st = aKV + ((j) & 3) * 32768; \
    int _j0 = (j) * 64; \
    _Pragma("unroll") \
    for (int _i = 0; _i < 2; _i++){ \
      int _gg = tid + 256*_i; \
      int _r = _gg >> 3, _c = _gg & 7; \
      uint32_t _d = SWZ((uint32_t)(_r*128 + _c*16)); \
      const size_t _srcK = baseq + 1024 + (size_t)(_j0 + _r) * 3072 + _c*8; \
      const size_t _srcV = baseq + 2048 + (size_t)(_j0 + _r) * 3072 + _c*8; \
      cpasync16(_st + _d,         QKVh + _srcK); \
      cpasync16(_st + 8192 + _d,  QKVl + _srcK); \
      cpasync16(_st + 16384 + _d, QKVh + _srcV); \
      cpasync16(_st + 24576 + _d, QKVl + _srcV); \
    } \
    CP_COMMIT(); \
  } while(0)

  uint32_t qfh[4][4], qfl[4][4];
  float m0 = -1e30f, m1 = -1e30f, l0 = 0.f, l1 = 0.f;
  float oa[8][4];
  #pragma unroll
  for (int nb = 0; nb < 8; nb++)
    #pragma unroll
    for (int r = 0; r < 4; r++) oa[nb][r] = 0.f;

  float scA[8][4], scB[8][4];

  #define SCORE(t, SC) do { \
    const uint32_t _st = aKV + ((t) & 3) * 32768; \
    _Pragma("unroll") \
    for (int _nb = 0; _nb < 8; _nb++) \
      _Pragma("unroll") \
      for (int _r = 0; _r < 4; _r++) SC[_nb][_r] = 0.f; \
    _Pragma("unroll") \
    for (int _s = 0; _s < 4; _s++){ \
      uint32_t _kh[4][4], _kl[4][4]; \
      _Pragma("unroll") \
      for (int _g = 0; _g < 4; _g++){ \
        uint32_t _off = SWZ((uint32_t)((_g*16 + rowB)*128 + _s*32 + kbB)); \
        ldsm4(_kh[_g], _st + _off); \
        ldsm4(_kl[_g], _st + 8192 + _off); \
      } \
      _Pragma("unroll") \
      for (int _g = 0; _g < 4; _g++){ \
        mma16816(SC[2*_g],   qfh[_s], _kh[_g]); \
        mma16816(SC[2*_g+1], qfh[_s], _kh[_g] + 2); \
        mma16816(SC[2*_g],   qfl[_s], _kh[_g]); \
        mma16816(SC[2*_g+1], qfl[_s], _kh[_g] + 2); \
        mma16816(SC[2*_g],   qfh[_s], _kl[_g]); \
        mma16816(SC[2*_g+1], qfh[_s], _kl[_g] + 2); \
      } \
    } \
  } while(0)

  #define STEP(t, CUR, NXT) do { \
    if ((t) + 2 < 32){ ISSUEKV((t) + 2); CP_WAIT1(); } \
    else if ((t) + 1 < 32){ CP_WAIT0(); } \
    __syncthreads(); \
    if ((t) + 1 < 32) SCORE((t) + 1, NXT); \
    float mx0 = -1e30f, mx1 = -1e30f; \
    _Pragma("unroll") \
    for (int nb = 0; nb < 8; nb++){ \
      mx0 = fmaxf(mx0, fmaxf(CUR[nb][0], CUR[nb][1])); \
      mx1 = fmaxf(mx1, fmaxf(CUR[nb][2], CUR[nb][3])); \
    } \
    mx0 = fmaxf(mx0, __shfl_xor_sync(0xffffffffu, mx0, 1)); \
    mx0 = fmaxf(mx0, __shfl_xor_sync(0xffffffffu, mx0, 2)); \
    mx1 = fmaxf(mx1, __shfl_xor_sync(0xffffffffu, mx1, 1)); \
    mx1 = fmaxf(mx1, __shfl_xor_sync(0xffffffffu, mx1, 2)); \
    float nm0 = fmaxf(m0, mx0), nm1 = fmaxf(m1, mx1); \
    float a0 = ex2f((m0 - nm0) * C8L2E), a1 = ex2f((m1 - nm1) * C8L2E); \
    m0 = nm0; m1 = nm1; \
    float c0 = nm0 * C8L2E, c1 = nm1 * C8L2E; \
    float rs0 = 0.f, rs1 = 0.f; \
    uint32_t pfh[4][4], pfl[4][4]; \
    _Pragma("unroll") \
    for (int nb = 0; nb < 8; nb++){ \
      float p00 = ex2f(fmaf(CUR[nb][0], C8L2E, -c0)); \
      float p01 = ex2f(fmaf(CUR[nb][1], C8L2E, -c0)); \
      float p10 = ex2f(fmaf(CUR[nb][2], C8L2E, -c1)); \
      float p11 = ex2f(fmaf(CUR[nb][3], C8L2E, -c1)); \
      rs0 += p00 + p01; rs1 += p10 + p11; \
      __nv_bfloat162 h0 = __floats2bfloat162_rn(p00, p01); \
      __nv_bfloat162 h1 = __floats2bfloat162_rn(p10, p11); \
      __nv_bfloat162 lo0 = __floats2bfloat162_rn(p00 - __bfloat162float(h0.x), \
                                                 p01 - __bfloat162float(h0.y)); \
      __nv_bfloat162 lo1 = __floats2bfloat162_rn(p10 - __bfloat162float(h1.x), \
                                                 p11 - __bfloat162float(h1.y)); \
      int j = nb >> 1, rq = (nb & 1) * 2; \
      pfh[j][rq]   = *(uint32_t*)&h0;  pfh[j][rq+1] = *(uint32_t*)&h1; \
      pfl[j][rq]   = *(uint32_t*)&lo0; pfl[j][rq+1] = *(uint32_t*)&lo1; \
    } \
    rs0 += __shfl_xor_sync(0xffffffffu, rs0, 1); \
    rs0 += __shfl_xor_sync(0xffffffffu, rs0, 2); \
    rs1 += __shfl_xor_sync(0xffffffffu, rs1, 1); \
    rs1 += __shfl_xor_sync(0xffffffffu, rs1, 2); \
    l0 = l0 * a0 + rs0; l1 = l1 * a1 + rs1; \
    _Pragma("unroll") \
    for (int nb = 0; nb < 8; nb++){ \
      oa[nb][0] *= a0; oa[nb][1] *= a0; oa[nb][2] *= a1; oa[nb][3] *= a1; \
    } \
    const uint32_t _pst = aKV + ((t) & 3) * 32768; \
    _Pragma("unroll") \
    for (int _s = 0; _s < 4; _s++){ \
      uint32_t _vh[4][4], _vl[4][4]; \
      _Pragma("unroll") \
      for (int _g = 0; _g < 4; _g++){ \
        uint32_t _off = SWZ((uint32_t)((_s*16 + kvr)*128 + (_g*16 + ncb)*2)); \
        ldsm4t(_vh[_g], _pst + 16384 + _off); \
        ldsm4t(_vl[_g], _pst + 24576 + _off); \
      } \
      _Pragma("unroll") \
      for (int _g = 0; _g < 4; _g++){ \
        mma16816(oa[2*_g],   pfh[_s], _vh[_g]); \
        mma16816(oa[2*_g+1], pfh[_s], _vh[_g] + 2); \
        mma16816(oa[2*_g],   pfl[_s], _vh[_g]); \
        mma16816(oa[2*_g+1], pfl[_s], _vh[_g] + 2); \
        mma16816(oa[2*_g],   pfh[_s], _vl[_g]); \
        mma16816(oa[2*_g+1], pfh[_s], _vl[_g] + 2); \
      } \
    } \
  } while(0)

  ISSUEKV(0); ISSUEKV(1);
  CP_WAIT1();
  __syncthreads();
  #pragma unroll
  for (int s = 0; s < 4; s++){
    uint32_t off = SWZ((uint32_t)((wm + rowA)*128 + s*32 + kbA));
    ldsm4(qfh[s], aQ + off);
    ldsm4(qfl[s], aQ + 16384 + off);
  }
  SCORE(0, scA);

  #pragma unroll 1
  for (int jt = 0; jt < 32; jt += 2){
    STEP(jt,     scA, scB);
    STEP(jt + 1, scB, scA);
  }
  #undef STEP
  #undef SCORE
  #undef ISSUEKV

  const int er = lane >> 2, ec = (lane & 3) * 2;
  float i0 = 1.0f / l0, i1 = 1.0f / l1;
  const int r0 = q0 + wm + er;
  #pragma unroll
  for (int nb = 0; nb < 8; nb++){
    int col = nb*8 + ec;
    float v0 = oa[nb][0]*i0, v1 = oa[nb][1]*i0;
    float v2 = oa[nb][2]*i1, v3 = oa[nb][3]*i1;
    __nv_bfloat162 h0 = __floats2bfloat162_rn(v0, v1);
    __nv_bfloat162 h1 = __floats2bfloat162_rn(v2, v3);
    __nv_bfloat162 lo0 = __floats2bfloat162_rn(v0 - __bfloat162float(h0.x),
                                               v1 - __bfloat162float(h0.y));
    __nv_bfloat162 lo1 = __floats2bfloat162_rn(v2 - __bfloat162float(h1.x),
                                               v3 - __bfloat162float(h1.y));
    size_t i0x = baseo + (size_t)r0 * 1024 + col;
    size_t i1x = baseo + (size_t)(r0 + 8) * 1024 + col;
    *(__nv_bfloat162*)(Oh + i0x) = h0;
    *(__nv_bfloat162*)(Ol + i0x) = lo0;
    *(__nv_bfloat162*)(Oh + i1x) = h1;
    *(__nv_bfloat162*)(Ol + i1x) = lo1;
  }
}

// ======================= launch =======================
extern "C" void kernel_launch(void* const* d_in, const int* in_sizes, int n_in,
                              void* d_out, int out_size)
{
  (void)in_sizes; (void)n_in; (void)out_size;
  const float* x   = (const float*)d_in[0];
  const float* Wk  = (const float*)d_in[2];
  const float* Wq  = (const float*)d_in[3];
  const float* Wv  = (const float*)d_in[4];
  const float* Wfc = (const float*)d_in[5];
  const float* bfc = (const float*)d_in[6];
  const float* g1  = (const float*)d_in[7];
  const float* b1  = (const float*)d_in[8];
  const float* g2  = (const float*)d_in[9];
  const float* b2  = (const float*)d_in[10];
  const float* W1  = (const float*)d_in[11];
  const float* bf1 = (const float*)d_in[12];
  const float* W2  = (const float*)d_in[13];
  const float* bf2 = (const float*)d_in[14];
  float* out = (float*)d_out;

  __nv_bfloat16 *xlh,*xll,*qkvh,*qkvl,*oh,*ol,*hh,*hl;
  __nv_bfloat16 *wqkvh,*wqkvl,*wfh,*wfl,*w1h,*w1l,*w2h,*w2l;
  float *x2;
  cudaGetSymbolAddress((void**)&xlh, g_xlh); cudaGetSymbolAddress((void**)&xll, g_xll);
  cudaGetSymbolAddress((void**)&qkvh, g_qkvh); cudaGetSymbolAddress((void**)&qkvl, g_qkvl);
  cudaGetSymbolAddress((void**)&oh, g_oh); cudaGetSymbolAddress((void**)&ol, g_ol);
  cudaGetSymbolAddress((void**)&x2, g_x2);
  cudaGetSymbolAddress((void**)&hh, g_hh); cudaGetSymbolAddress((void**)&hl, g_hl);
  cudaGetSymbolAddress((void**)&wqkvh, g_wqkvh); cudaGetSymbolAddress((void**)&wqkvl, g_wqkvl);
  cudaGetSymbolAddress((void**)&wfh, g_wfh); cudaGetSymbolAddress((void**)&wfl, g_wfl);
  cudaGetSymbolAddress((void**)&w1h, g_w1h); cudaGetSymbolAddress((void**)&w1l, g_w1l);
  cudaGetSymbolAddress((void**)&w2h, g_w2h); cudaGetSymbolAddress((void**)&w2l, g_w2l);

  static int smem_set = 0;
  if (!smem_set){
    cudaFuncSetAttribute(gemm_mma, cudaFuncAttributeMaxDynamicSharedMemorySize, 196608);
    cudaFuncSetAttribute(attn_mma, cudaFuncAttributeMaxDynamicSharedMemorySize, 163840);
    smem_set = 1;
  }

  const int M = 8192, D = 1024;
  const int GSM = 196608;   // 2 stages x 96KB
  const int ASM = 163840;   // Q 32KB + 4x32KB KV ring

  // fused: weight transpose/split (12288 blocks) + LN1 (8192 blocks)
  prep_all<<<20480, 256>>>(Wq, Wk, Wv, Wfc, W1, W2,
                           wqkvh, wqkvl, wfh, wfl, w1h, w1l, w2h, w2l,
                           x, g1, b1, xlh, xll);

  dim3 gQKV(3*D/256, M/128);   // (12, 64)
  dim3 gD(D/256, M/128);       // (4, 64)
  dim3 gF(4*D/256, M/128);     // (16, 64)

  gemm_mma<<<gQKV, 256, GSM>>>(xlh, xll, wqkvh, wqkvl, nullptr, nullptr, nullptr,
                               qkvh, qkvl, M, 3*D, D, 0, 1);
  attn_mma<<<dim3(16, 16, 4), 256, ASM>>>(qkvh, qkvl, oh, ol);
  gemm_mma<<<gD, 256, GSM>>>(oh, ol, wfh, wfl, bfc, x, x2, nullptr, nullptr,
                             M, D, D, 0, 0);
  ln1024_split<<<M, 256>>>(x2, g2, b2, xlh, xll);
  gemm_mma<<<gF, 256, GSM>>>(xlh, xll, w1h, w1l, bf1, nullptr, nullptr, hh, hl,
                             M, 4*D, D, 1, 1);
  gemm_mma<<<gD, 256, GSM>>>(hh, hl, w2h, w2l, bf2, x2, out, nullptr, nullptr,
                             M, D, 4*D, 0, 0);
}